// round 7
// baseline (speedup 1.0000x reference)
#include <cuda_runtime.h>
#include <math.h>

#define VOCAB 50000
#define Bx 256
#define Rn 20
#define Wn 100
#define Dn 128
#define Hn 64
#define NCOL (Dn*Hn)   // 8192
#define BT 32
#define CT 128

// Scratch (allocation-free rule: __device__ globals)
__device__ float g_user_emb[Bx*Rn*Dn];   // 2.62 MB
__device__ float g_item_emb[Bx*Rn*Dn];   // 2.62 MB
__device__ float g_q_emb[Bx*Dn];         // 128 KB
__device__ float g_V[Bx*Dn];             // 128 KB
__device__ float g_wexp[VOCAB];          // 200 KB: exp(tanh(emb[v].w_self + b))

// ---------------------------------------------------------------------------
// Kernel 0: per-vocab score table. Word scores are doc-independent:
//   wexp[v] = exp(tanh(emb[v] . w_self + b_self)).
// One warp per vocab row (lane holds 4 dims). Also pre-warms L2 with the
// embedding table for the gather kernel.
// ---------------------------------------------------------------------------
__global__ __launch_bounds__(256) void proj_kernel(
        const float* __restrict__ emb,
        const float* __restrict__ w_self,
        const float* __restrict__ b_self) {
    const int gw   = (blockIdx.x*blockDim.x + threadIdx.x) >> 5;
    const int lane = threadIdx.x & 31;
    if (gw >= VOCAB) return;
    const float4 e = *(const float4*)(emb + (size_t)gw*Dn + lane*4);
    const float4 w = *(const float4*)(w_self + lane*4);
    float s = e.x*w.x + e.y*w.y + e.z*w.z + e.w*w.w;
    #pragma unroll
    for (int off = 16; off > 0; off >>= 1)
        s += __shfl_xor_sync(0xffffffffu, s, off);
    if (lane == 0) g_wexp[gw] = __expf(tanhf(s + b_self[0]));
}

// ---------------------------------------------------------------------------
// Kernel 1: doc embedding = single weighted-gather pass.
// One block (512 thr = 16 warps) per doc. Weights come from the wexp table
// (4 B/word); embeddings are loaded once, FMA'd immediately (no register
// retention -> low regs -> 3 blocks/SM). Pair layout: pair p -> word 2p in
// lanes 0-15, word 2p+1 in lanes 16-31; lane l4 covers dims [l4*4..+3] and
// [64+l4*4..+3]. Softmax normalization deferred to the final divide.
// ---------------------------------------------------------------------------
__global__ __launch_bounds__(512, 3) void doc_embed_kernel(
        const int* __restrict__ user,
        const int* __restrict__ item,
        const int* __restrict__ query,
        const float* __restrict__ emb) {
    __shared__ float sscore[Wn];                      // wexp per word
    __shared__ int   swords[Wn];
    __shared__ __align__(16) float spart[16][Dn + 4]; // 8.4 KB warp partials

    const int tid  = threadIdx.x;
    const int lane = tid & 31;
    const int wid  = tid >> 5;       // 0..15
    const int l4   = lane & 15;
    const int hl   = lane >> 4;      // 0 = word A, 1 = word B
    const int doc  = blockIdx.x;

    const int* words;
    float* outp;
    if (doc < Bx*Rn)        { words = user + doc*Wn;                outp = g_user_emb + doc*Dn; }
    else if (doc < 2*Bx*Rn) { int j = doc - Bx*Rn;   words = item  + j*Wn; outp = g_item_emb + j*Dn; }
    else                    { int j = doc - 2*Bx*Rn; words = query + j*Wn; outp = g_q_emb    + j*Dn; }

    // Phase 1: indices + per-word weights from the table (4 B each).
    if (tid < Wn) {
        const int w = __ldg(words + tid);
        swords[tid] = w;
        sscore[tid] = __ldg(g_wexp + w);
    }
    __syncthreads();

    // Phase 2: weighted gather-sum with UN-normalized weights.
    float4 aL = make_float4(0.f,0.f,0.f,0.f);
    float4 aH = make_float4(0.f,0.f,0.f,0.f);
    #pragma unroll
    for (int i = 0; i < 4; i++) {
        const int p = wid + 16*i;
        if (p < Wn/2) {
            const int   w2 = 2*p + hl;
            const float s  = sscore[w2];                 // half-warp broadcast
            const float* base = emb + (size_t)swords[w2]*Dn;
            const float4 eL = *(const float4*)(base + l4*4);
            const float4 eH = *(const float4*)(base + 64 + l4*4);
            aL.x += s*eL.x; aL.y += s*eL.y; aL.z += s*eL.z; aL.w += s*eL.w;
            aH.x += s*eH.x; aH.y += s*eH.y; aH.z += s*eH.z; aH.w += s*eH.w;
        }
    }
    // Combine word-A/word-B halves (same dims in lanes l and l+16).
    aL.x += __shfl_xor_sync(0xffffffffu, aL.x, 16);
    aL.y += __shfl_xor_sync(0xffffffffu, aL.y, 16);
    aL.z += __shfl_xor_sync(0xffffffffu, aL.z, 16);
    aL.w += __shfl_xor_sync(0xffffffffu, aL.w, 16);
    aH.x += __shfl_xor_sync(0xffffffffu, aH.x, 16);
    aH.y += __shfl_xor_sync(0xffffffffu, aH.y, 16);
    aH.z += __shfl_xor_sync(0xffffffffu, aH.z, 16);
    aH.w += __shfl_xor_sync(0xffffffffu, aH.w, 16);
    if (hl == 0) {
        *(float4*)(&spart[wid][l4*4])      = aL;
        *(float4*)(&spart[wid][64 + l4*4]) = aH;
    }
    __syncthreads();

    // Final: warps 0-3 redundantly compute the softmax denominator (LDS+SHFL,
    // identical op order per warp), reduce 16 partials, divide once.
    if (tid < Dn) {
        float e0 = sscore[lane];
        float e1 = sscore[lane + 32];
        float e2 = sscore[lane + 64];
        float e3 = (lane < Wn - 96) ? sscore[lane + 96] : 0.f;
        float ssum = (e0 + e1) + (e2 + e3);
        #pragma unroll
        for (int off = 16; off > 0; off >>= 1)
            ssum += __shfl_xor_sync(0xffffffffu, ssum, off);

        float r = 0.f;
        #pragma unroll
        for (int w = 0; w < 16; w++) r += spart[w][tid];
        outp[tid] = r / ssum;
    }
}

// ---------------------------------------------------------------------------
// Kernel 2: fused  V[b,d] = sum_h tanh(q_b . Wq[:, d*64+h] + bq) * w_red[h]
// Batch-tiled GEMM (BT=32 batches reuse each Wq element), col tile CT=128.
// pq (8 MB) is never materialized.
// ---------------------------------------------------------------------------
__global__ void pq_kernel(const float* __restrict__ Wq,
                          const float* __restrict__ bq,
                          const float* __restrict__ w_red) {
    __shared__ __align__(16) float QsT[Dn][BT + 4];   // transposed, padded
    __shared__ float red[BT][CT + 1];

    const int tid  = threadIdx.x;        // 128 threads
    const int col0 = blockIdx.x * CT;
    const int b0   = blockIdx.y * BT;

    #pragma unroll 4
    for (int b = 0; b < BT; b++)
        QsT[tid][b] = g_q_emb[(b0 + b)*Dn + tid];
    __syncthreads();

    float acc[BT];
    #pragma unroll
    for (int b = 0; b < BT; b++) acc[b] = 0.f;

    const int col = col0 + tid;
    const float* wqp = Wq + col;
    #pragma unroll 4
    for (int k = 0; k < Dn; k++) {
        const float wv = wqp[(size_t)k * NCOL];
        const float4* q4 = (const float4*)(&QsT[k][0]);
        #pragma unroll
        for (int i = 0; i < BT/4; i++) {
            float4 q = q4[i];
            acc[4*i+0] += q.x * wv;
            acc[4*i+1] += q.y * wv;
            acc[4*i+2] += q.z * wv;
            acc[4*i+3] += q.w * wv;
        }
    }

    const float bqv = bq[col];
    const float wr  = w_red[col & (Hn-1)];
    #pragma unroll
    for (int b = 0; b < BT; b++)
        red[b][tid] = tanhf(acc[b] + bqv) * wr;
    __syncthreads();

    // Reduce groups of 64 cols: 64 sums, 2 threads each
    const int s    = tid >> 1;      // 0..63
    const int b    = s >> 1;        // 0..31
    const int grp  = s & 1;
    const int part = tid & 1;
    float r = 0.f;
    const int base = grp*64 + part*32;
    #pragma unroll
    for (int j = 0; j < 32; j++) r += red[b][base + j];
    r += __shfl_xor_sync(0xffffffffu, r, 1);
    if (part == 0) {
        const int dd = (col0 >> 6) + grp;
        g_V[(b0 + b)*Dn + dd] = r;
    }
}

// ---------------------------------------------------------------------------
// Kernel 3: review attention (softmax over R=20) + final outputs
// One block per batch.
// ---------------------------------------------------------------------------
__global__ void attn_kernel(const float* __restrict__ pf_ptr,
                            float* __restrict__ out) {
    __shared__ float v[Dn];
    __shared__ float r_u[32], r_i[32];
    const int tid  = threadIdx.x;   // 128
    const int lane = tid & 31;
    const int wid  = tid >> 5;
    const int b    = blockIdx.x;

    v[tid] = g_V[b*Dn + tid];
    __syncthreads();

    for (int rr = wid; rr < Rn; rr += 4) {
        const float* ue = g_user_emb + (b*Rn + rr)*Dn;
        const float* ie = g_item_emb + (b*Rn + rr)*Dn;
        float pu = 0.f, pi = 0.f;
        #pragma unroll
        for (int j = 0; j < 4; j++) {
            const int d = lane + 32*j;
            const float vv = v[d];
            pu += ue[d]*vv;
            pi += ie[d]*vv;
        }
        #pragma unroll
        for (int off = 16; off > 0; off >>= 1) {
            pu += __shfl_xor_sync(0xffffffffu, pu, off);
            pi += __shfl_xor_sync(0xffffffffu, pi, off);
        }
        if (lane == 0) { r_u[rr] = pu; r_i[rr] = pi; }
    }
    __syncthreads();

    if (wid < 2) {
        float* rs = wid ? r_i : r_u;
        float x = (lane < Rn) ? rs[lane] : -1e30f;
        float m = x;
        #pragma unroll
        for (int off = 16; off > 0; off >>= 1)
            m = fmaxf(m, __shfl_xor_sync(0xffffffffu, m, off));
        float e = (lane < Rn) ? __expf(x - m) : 0.f;
        float ss = e;
        #pragma unroll
        for (int off = 16; off > 0; off >>= 1)
            ss += __shfl_xor_sync(0xffffffffu, ss, off);
        if (lane < Rn) rs[lane] = e / ss;
    }
    __syncthreads();

    float ue_acc = 0.f, ie_acc = 0.f;
    #pragma unroll
    for (int rr = 0; rr < Rn; rr++) {
        ue_acc += r_u[rr] * g_user_emb[(b*Rn + rr)*Dn + tid];
        ie_acc += r_i[rr] * g_item_emb[(b*Rn + rr)*Dn + tid];
    }
    const float pf = pf_ptr[0];
    out[b*Dn + tid]         = ue_acc + pf * g_q_emb[b*Dn + tid];
    out[Bx*Dn + b*Dn + tid] = ie_acc;
}

// ---------------------------------------------------------------------------
extern "C" void kernel_launch(void* const* d_in, const int* in_sizes, int n_in,
                              void* d_out, int out_size) {
    const int*   user   = (const int*)  d_in[0];
    const int*   item   = (const int*)  d_in[1];
    const int*   query  = (const int*)  d_in[2];
    const float* emb    = (const float*)d_in[3];
    const float* w_self = (const float*)d_in[4];
    const float* b_self = (const float*)d_in[5];
    const float* Wq     = (const float*)d_in[6];
    const float* bq     = (const float*)d_in[7];
    const float* w_red  = (const float*)d_in[8];
    const float* pf     = (const float*)d_in[9];
    float* out = (float*)d_out;

    proj_kernel<<<(VOCAB*32 + 255)/256, 256>>>(emb, w_self, b_self);

    doc_embed_kernel<<<2*Bx*Rn + Bx, 512>>>(user, item, query, emb);

    dim3 g2(NCOL/CT, Bx/BT);   // (64, 8)
    pq_kernel<<<g2, CT>>>(Wq, bq, w_red);

    attn_kernel<<<Bx, Dn>>>(pf, out);
}

// round 8
// speedup vs baseline: 1.2885x; 1.2885x over previous
#include <cuda_runtime.h>
#include <math.h>

#define VOCAB 50000
#define Bx 256
#define Rn 20
#define Wn 100
#define Dn 128
#define Hn 64
#define NCOL (Dn*Hn)   // 8192
#define BT 32
#define CT 128

// Scratch (allocation-free rule: __device__ globals)
__device__ float g_user_emb[Bx*Rn*Dn];   // 2.62 MB
__device__ float g_item_emb[Bx*Rn*Dn];   // 2.62 MB
__device__ float g_q_emb[Bx*Dn];         // 128 KB
__device__ float g_V[Bx*Dn];             // 128 KB
__device__ float g_wexp[VOCAB];          // 200 KB: exp(tanh(emb[v].w_self + b))

// ---------------------------------------------------------------------------
// Kernel 0: per-vocab score table. Word scores are doc-independent:
//   wexp[v] = exp(tanh(emb[v] . w_self + b_self)).
// One warp per vocab row. Also pre-warms L2 with the embedding table.
// ---------------------------------------------------------------------------
__global__ __launch_bounds__(256) void proj_kernel(
        const float* __restrict__ emb,
        const float* __restrict__ w_self,
        const float* __restrict__ b_self) {
    const int gw   = (blockIdx.x*blockDim.x + threadIdx.x) >> 5;
    const int lane = threadIdx.x & 31;
    if (gw >= VOCAB) return;
    const float4 e = *(const float4*)(emb + (size_t)gw*Dn + lane*4);
    const float4 w = *(const float4*)(w_self + lane*4);
    float s = e.x*w.x + e.y*w.y + e.z*w.z + e.w*w.w;
    #pragma unroll
    for (int off = 16; off > 0; off >>= 1)
        s += __shfl_xor_sync(0xffffffffu, s, off);
    if (lane == 0) g_wexp[gw] = __expf(tanhf(s + b_self[0]));
}

// ---------------------------------------------------------------------------
// Kernel 1: doc embedding = single weighted-gather pass.
// One block (512 thr = 16 warps) per doc. Weights from the wexp table.
// Pair layout: pair p -> word 2p in lanes 0-15, word 2p+1 in lanes 16-31;
// lane l4 covers dims [l4*4..+3] and [64+l4*4..+3].
// Explicit prefetch: 8 float4 loads issued back-to-back (MLP=8) BEFORE any
// FMA; launch_bounds(512,2) = 64 regs so nothing spills.
// Softmax normalization deferred to the final divide.
// ---------------------------------------------------------------------------
__global__ __launch_bounds__(512, 2) void doc_embed_kernel(
        const int* __restrict__ user,
        const int* __restrict__ item,
        const int* __restrict__ query,
        const float* __restrict__ emb) {
    __shared__ float sscore[Wn];                      // wexp per word
    __shared__ int   swords[Wn];
    __shared__ __align__(16) float spart[16][Dn + 4]; // 8.4 KB warp partials

    const int tid  = threadIdx.x;
    const int lane = tid & 31;
    const int wid  = tid >> 5;       // 0..15
    const int l4   = lane & 15;
    const int hl   = lane >> 4;      // 0 = word A, 1 = word B
    const int doc  = blockIdx.x;

    const int* words;
    float* outp;
    if (doc < Bx*Rn)        { words = user + doc*Wn;                outp = g_user_emb + doc*Dn; }
    else if (doc < 2*Bx*Rn) { int j = doc - Bx*Rn;   words = item  + j*Wn; outp = g_item_emb + j*Dn; }
    else                    { int j = doc - 2*Bx*Rn; words = query + j*Wn; outp = g_q_emb    + j*Dn; }

    // Phase 1: indices + per-word weights from the table (4 B each).
    if (tid < Wn) {
        const int w = __ldg(words + tid);
        swords[tid] = w;
        sscore[tid] = __ldg(g_wexp + w);
    }
    __syncthreads();

    // Phase 2a: read scores + base pointers for this warp's 4 pairs.
    float        s[4];
    const float* base[4];
    #pragma unroll
    for (int i = 0; i < 4; i++) {
        const int p = wid + 16*i;
        if (p < Wn/2) {
            const int w2 = 2*p + hl;
            s[i]    = sscore[w2];
            base[i] = emb + (size_t)swords[w2]*Dn;
        } else { s[i] = 0.f; base[i] = emb; }
    }
    // Phase 2b: issue all 8 float4 loads (batched, MLP=8).
    float4 eL[4], eH[4];
    #pragma unroll
    for (int i = 0; i < 4; i++) {
        eL[i] = *(const float4*)(base[i] + l4*4);
        eH[i] = *(const float4*)(base[i] + 64 + l4*4);
    }
    // Phase 2c: weighted accumulate (un-normalized weights).
    float4 aL = make_float4(0.f,0.f,0.f,0.f);
    float4 aH = make_float4(0.f,0.f,0.f,0.f);
    #pragma unroll
    for (int i = 0; i < 4; i++) {
        aL.x += s[i]*eL[i].x; aL.y += s[i]*eL[i].y;
        aL.z += s[i]*eL[i].z; aL.w += s[i]*eL[i].w;
        aH.x += s[i]*eH[i].x; aH.y += s[i]*eH[i].y;
        aH.z += s[i]*eH[i].z; aH.w += s[i]*eH[i].w;
    }
    // Combine word-A/word-B halves (same dims in lanes l and l+16).
    aL.x += __shfl_xor_sync(0xffffffffu, aL.x, 16);
    aL.y += __shfl_xor_sync(0xffffffffu, aL.y, 16);
    aL.z += __shfl_xor_sync(0xffffffffu, aL.z, 16);
    aL.w += __shfl_xor_sync(0xffffffffu, aL.w, 16);
    aH.x += __shfl_xor_sync(0xffffffffu, aH.x, 16);
    aH.y += __shfl_xor_sync(0xffffffffu, aH.y, 16);
    aH.z += __shfl_xor_sync(0xffffffffu, aH.z, 16);
    aH.w += __shfl_xor_sync(0xffffffffu, aH.w, 16);
    if (hl == 0) {
        *(float4*)(&spart[wid][l4*4])      = aL;
        *(float4*)(&spart[wid][64 + l4*4]) = aH;
    }
    __syncthreads();

    // Final: warps 0-3 redundantly compute the softmax denominator (LDS+SHFL,
    // identical op order per warp), reduce 16 partials, divide once.
    if (tid < Dn) {
        float e0 = sscore[lane];
        float e1 = sscore[lane + 32];
        float e2 = sscore[lane + 64];
        float e3 = (lane < Wn - 96) ? sscore[lane + 96] : 0.f;
        float ssum = (e0 + e1) + (e2 + e3);
        #pragma unroll
        for (int off = 16; off > 0; off >>= 1)
            ssum += __shfl_xor_sync(0xffffffffu, ssum, off);

        float r = 0.f;
        #pragma unroll
        for (int w = 0; w < 16; w++) r += spart[w][tid];
        outp[tid] = r / ssum;
    }
}

// ---------------------------------------------------------------------------
// Kernel 2: fused  V[b,d] = sum_h tanh(q_b . Wq[:, d*64+h] + bq) * w_red[h]
// Batch-tiled GEMM (BT=32 batches reuse each Wq element), col tile CT=128.
// pq (8 MB) is never materialized.
// ---------------------------------------------------------------------------
__global__ void pq_kernel(const float* __restrict__ Wq,
                          const float* __restrict__ bq,
                          const float* __restrict__ w_red) {
    __shared__ __align__(16) float QsT[Dn][BT + 4];   // transposed, padded
    __shared__ float red[BT][CT + 1];

    const int tid  = threadIdx.x;        // 128 threads
    const int col0 = blockIdx.x * CT;
    const int b0   = blockIdx.y * BT;

    #pragma unroll 4
    for (int b = 0; b < BT; b++)
        QsT[tid][b] = g_q_emb[(b0 + b)*Dn + tid];
    __syncthreads();

    float acc[BT];
    #pragma unroll
    for (int b = 0; b < BT; b++) acc[b] = 0.f;

    const int col = col0 + tid;
    const float* wqp = Wq + col;
    #pragma unroll 4
    for (int k = 0; k < Dn; k++) {
        const float wv = wqp[(size_t)k * NCOL];
        const float4* q4 = (const float4*)(&QsT[k][0]);
        #pragma unroll
        for (int i = 0; i < BT/4; i++) {
            float4 q = q4[i];
            acc[4*i+0] += q.x * wv;
            acc[4*i+1] += q.y * wv;
            acc[4*i+2] += q.z * wv;
            acc[4*i+3] += q.w * wv;
        }
    }

    const float bqv = bq[col];
    const float wr  = w_red[col & (Hn-1)];
    #pragma unroll
    for (int b = 0; b < BT; b++)
        red[b][tid] = tanhf(acc[b] + bqv) * wr;
    __syncthreads();

    // Reduce groups of 64 cols: 64 sums, 2 threads each
    const int s    = tid >> 1;      // 0..63
    const int b    = s >> 1;        // 0..31
    const int grp  = s & 1;
    const int part = tid & 1;
    float r = 0.f;
    const int base = grp*64 + part*32;
    #pragma unroll
    for (int j = 0; j < 32; j++) r += red[b][base + j];
    r += __shfl_xor_sync(0xffffffffu, r, 1);
    if (part == 0) {
        const int dd = (col0 >> 6) + grp;
        g_V[(b0 + b)*Dn + dd] = r;
    }
}

// ---------------------------------------------------------------------------
// Kernel 3: review attention (softmax over R=20) + final outputs.
// Grid (Bx, 2): blockIdx.y = 0 -> user entity, 1 -> item entity.
// ---------------------------------------------------------------------------
__global__ void attn_kernel(const float* __restrict__ pf_ptr,
                            float* __restrict__ out) {
    __shared__ float v[Dn];
    __shared__ float rw[32];
    const int tid  = threadIdx.x;   // 128
    const int lane = tid & 31;
    const int wid  = tid >> 5;
    const int b    = blockIdx.x;
    const int side = blockIdx.y;    // 0 = user, 1 = item

    const float* embp = side ? g_item_emb : g_user_emb;

    v[tid] = g_V[b*Dn + tid];
    __syncthreads();

    for (int rr = wid; rr < Rn; rr += 4) {
        const float* e = embp + (b*Rn + rr)*Dn;
        float p = 0.f;
        #pragma unroll
        for (int j = 0; j < 4; j++) {
            const int d = lane + 32*j;
            p += e[d]*v[d];
        }
        #pragma unroll
        for (int off = 16; off > 0; off >>= 1)
            p += __shfl_xor_sync(0xffffffffu, p, off);
        if (lane == 0) rw[rr] = p;
    }
    __syncthreads();

    if (wid == 0) {
        float x = (lane < Rn) ? rw[lane] : -1e30f;
        float m = x;
        #pragma unroll
        for (int off = 16; off > 0; off >>= 1)
            m = fmaxf(m, __shfl_xor_sync(0xffffffffu, m, off));
        float e = (lane < Rn) ? __expf(x - m) : 0.f;
        float ss = e;
        #pragma unroll
        for (int off = 16; off > 0; off >>= 1)
            ss += __shfl_xor_sync(0xffffffffu, ss, off);
        if (lane < Rn) rw[lane] = e / ss;
    }
    __syncthreads();

    float acc = 0.f;
    #pragma unroll
    for (int rr = 0; rr < Rn; rr++)
        acc += rw[rr] * embp[(b*Rn + rr)*Dn + tid];

    if (side == 0) {
        out[b*Dn + tid] = acc + pf_ptr[0] * g_q_emb[b*Dn + tid];
    } else {
        out[Bx*Dn + b*Dn + tid] = acc;
    }
}

// ---------------------------------------------------------------------------
extern "C" void kernel_launch(void* const* d_in, const int* in_sizes, int n_in,
                              void* d_out, int out_size) {
    const int*   user   = (const int*)  d_in[0];
    const int*   item   = (const int*)  d_in[1];
    const int*   query  = (const int*)  d_in[2];
    const float* emb    = (const float*)d_in[3];
    const float* w_self = (const float*)d_in[4];
    const float* b_self = (const float*)d_in[5];
    const float* Wq     = (const float*)d_in[6];
    const float* bq     = (const float*)d_in[7];
    const float* w_red  = (const float*)d_in[8];
    const float* pf     = (const float*)d_in[9];
    float* out = (float*)d_out;

    proj_kernel<<<(VOCAB*32 + 255)/256, 256>>>(emb, w_self, b_self);

    doc_embed_kernel<<<2*Bx*Rn + Bx, 512>>>(user, item, query, emb);

    dim3 g2(NCOL/CT, Bx/BT);   // (64, 8)
    pq_kernel<<<g2, CT>>>(Wq, bq, w_red);

    dim3 g3(Bx, 2);
    attn_kernel<<<g3, Dn>>>(pf, out);
}

// round 9
// speedup vs baseline: 1.6975x; 1.3174x over previous
#include <cuda_runtime.h>
#include <math.h>

#define VOCAB 50000
#define Bx 256
#define Rn 20
#define Wn 100
#define Dn 128
#define Hn 64
#define NCOL (Dn*Hn)   // 8192
#define BT 32
#define CT 128
#define DPB 16         // docs per block (one warp each)

// Scratch (allocation-free rule: __device__ globals)
__device__ float g_user_emb[Bx*Rn*Dn];   // 2.62 MB
__device__ float g_item_emb[Bx*Rn*Dn];   // 2.62 MB
__device__ float g_q_emb[Bx*Dn];         // 128 KB
__device__ float g_V[Bx*Dn];             // 128 KB
__device__ float g_wexp[VOCAB];          // 200 KB: exp(tanh(emb[v].w_self + b))

// ---------------------------------------------------------------------------
// Kernel 0: per-vocab score table. Word scores are doc-independent:
//   wexp[v] = exp(tanh(emb[v] . w_self + b_self)).
// One warp per vocab row. Also pre-warms L2 with the embedding table.
// ---------------------------------------------------------------------------
__global__ __launch_bounds__(256) void proj_kernel(
        const float* __restrict__ emb,
        const float* __restrict__ w_self,
        const float* __restrict__ b_self) {
    const int gw   = (blockIdx.x*blockDim.x + threadIdx.x) >> 5;
    const int lane = threadIdx.x & 31;
    if (gw >= VOCAB) return;
    const float4 e = *(const float4*)(emb + (size_t)gw*Dn + lane*4);
    const float4 w = *(const float4*)(w_self + lane*4);
    float s = e.x*w.x + e.y*w.y + e.z*w.z + e.w*w.w;
    #pragma unroll
    for (int off = 16; off > 0; off >>= 1)
        s += __shfl_xor_sync(0xffffffffu, s, off);
    if (lane == 0) g_wexp[gw] = __expf(tanhf(s + b_self[0]));
}

// ---------------------------------------------------------------------------
// Kernel 1: doc embedding — ONE WARP PER DOC, zero barriers, zero shuffles.
// Lane l holds dims [l*4..l*4+3]; one LDG.128 per word covers the full row.
// idx+weight packed as int2 in smem (one uniform LDS.64 per iteration).
// Softmax normalization deferred: acc = sum(w_i * e_i), out = acc / sum(w_i).
// ---------------------------------------------------------------------------
__global__ __launch_bounds__(512, 2) void doc_embed_kernel(
        const int* __restrict__ user,
        const int* __restrict__ item,
        const int* __restrict__ query,
        const float* __restrict__ emb) {
    __shared__ int2 sp[DPB][Wn];   // (word index, weight bits): 12.8 KB

    const int lane = threadIdx.x & 31;
    const int wid  = threadIdx.x >> 5;               // 0..15
    const int doc  = blockIdx.x * DPB + wid;         // 656*16 = 10496 exact

    const int* words;
    float* outp;
    if (doc < Bx*Rn)        { words = user + doc*Wn;                outp = g_user_emb + doc*Dn; }
    else if (doc < 2*Bx*Rn) { int j = doc - Bx*Rn;   words = item  + j*Wn; outp = g_item_emb + j*Dn; }
    else                    { int j = doc - 2*Bx*Rn; words = query + j*Wn; outp = g_q_emb    + j*Dn; }

    // Stage this doc's indices + weights (per-warp, no block sync).
    for (int k = lane; k < Wn; k += 32) {
        const int w = __ldg(words + k);
        sp[wid][k] = make_int2(w, __float_as_int(__ldg(g_wexp + w)));
    }
    __syncwarp();

    // Main gather loop: 100 independent LDG.128, FMA into per-lane float4.
    float4 acc = make_float4(0.f, 0.f, 0.f, 0.f);
    float  ssum = 0.f;
    #pragma unroll 8
    for (int i = 0; i < Wn; i++) {
        const int2  pr  = sp[wid][i];            // uniform LDS.64 broadcast
        const float s   = __int_as_float(pr.y);
        const float4 e  = *(const float4*)(emb + (size_t)pr.x*Dn + lane*4);
        ssum  += s;
        acc.x += s*e.x; acc.y += s*e.y; acc.z += s*e.z; acc.w += s*e.w;
    }

    const float inv = 1.f / ssum;
    float4 o = make_float4(acc.x*inv, acc.y*inv, acc.z*inv, acc.w*inv);
    *(float4*)(outp + lane*4) = o;
}

// ---------------------------------------------------------------------------
// Kernel 2: fused  V[b,d] = sum_h tanh(q_b . Wq[:, d*64+h] + bq) * w_red[h]
// Batch-tiled GEMM (BT=32 batches reuse each Wq element), col tile CT=128.
// pq (8 MB) is never materialized.
// ---------------------------------------------------------------------------
__global__ void pq_kernel(const float* __restrict__ Wq,
                          const float* __restrict__ bq,
                          const float* __restrict__ w_red) {
    __shared__ __align__(16) float QsT[Dn][BT + 4];   // transposed, padded
    __shared__ float red[BT][CT + 1];

    const int tid  = threadIdx.x;        // 128 threads
    const int col0 = blockIdx.x * CT;
    const int b0   = blockIdx.y * BT;

    #pragma unroll 4
    for (int b = 0; b < BT; b++)
        QsT[tid][b] = g_q_emb[(b0 + b)*Dn + tid];
    __syncthreads();

    float acc[BT];
    #pragma unroll
    for (int b = 0; b < BT; b++) acc[b] = 0.f;

    const int col = col0 + tid;
    const float* wqp = Wq + col;
    #pragma unroll 4
    for (int k = 0; k < Dn; k++) {
        const float wv = wqp[(size_t)k * NCOL];
        const float4* q4 = (const float4*)(&QsT[k][0]);
        #pragma unroll
        for (int i = 0; i < BT/4; i++) {
            float4 q = q4[i];
            acc[4*i+0] += q.x * wv;
            acc[4*i+1] += q.y * wv;
            acc[4*i+2] += q.z * wv;
            acc[4*i+3] += q.w * wv;
        }
    }

    const float bqv = bq[col];
    const float wr  = w_red[col & (Hn-1)];
    #pragma unroll
    for (int b = 0; b < BT; b++)
        red[b][tid] = tanhf(acc[b] + bqv) * wr;
    __syncthreads();

    // Reduce groups of 64 cols: 64 sums, 2 threads each
    const int s    = tid >> 1;      // 0..63
    const int b    = s >> 1;        // 0..31
    const int grp  = s & 1;
    const int part = tid & 1;
    float r = 0.f;
    const int base = grp*64 + part*32;
    #pragma unroll
    for (int j = 0; j < 32; j++) r += red[b][base + j];
    r += __shfl_xor_sync(0xffffffffu, r, 1);
    if (part == 0) {
        const int dd = (col0 >> 6) + grp;
        g_V[(b0 + b)*Dn + dd] = r;
    }
}

// ---------------------------------------------------------------------------
// Kernel 3: review attention (softmax over R=20) + final outputs.
// Grid (Bx, 2): blockIdx.y = 0 -> user entity, 1 -> item entity.
// ---------------------------------------------------------------------------
__global__ void attn_kernel(const float* __restrict__ pf_ptr,
                            float* __restrict__ out) {
    __shared__ float v[Dn];
    __shared__ float rw[32];
    const int tid  = threadIdx.x;   // 128
    const int lane = tid & 31;
    const int wid  = tid >> 5;
    const int b    = blockIdx.x;
    const int side = blockIdx.y;    // 0 = user, 1 = item

    const float* embp = side ? g_item_emb : g_user_emb;

    v[tid] = g_V[b*Dn + tid];
    __syncthreads();

    for (int rr = wid; rr < Rn; rr += 4) {
        const float* e = embp + (b*Rn + rr)*Dn;
        float p = 0.f;
        #pragma unroll
        for (int j = 0; j < 4; j++) {
            const int d = lane + 32*j;
            p += e[d]*v[d];
        }
        #pragma unroll
        for (int off = 16; off > 0; off >>= 1)
            p += __shfl_xor_sync(0xffffffffu, p, off);
        if (lane == 0) rw[rr] = p;
    }
    __syncthreads();

    if (wid == 0) {
        float x = (lane < Rn) ? rw[lane] : -1e30f;
        float m = x;
        #pragma unroll
        for (int off = 16; off > 0; off >>= 1)
            m = fmaxf(m, __shfl_xor_sync(0xffffffffu, m, off));
        float e = (lane < Rn) ? __expf(x - m) : 0.f;
        float ss = e;
        #pragma unroll
        for (int off = 16; off > 0; off >>= 1)
            ss += __shfl_xor_sync(0xffffffffu, ss, off);
        if (lane < Rn) rw[lane] = e / ss;
    }
    __syncthreads();

    float acc = 0.f;
    #pragma unroll
    for (int rr = 0; rr < Rn; rr++)
        acc += rw[rr] * embp[(b*Rn + rr)*Dn + tid];

    if (side == 0) {
        out[b*Dn + tid] = acc + pf_ptr[0] * g_q_emb[b*Dn + tid];
    } else {
        out[Bx*Dn + b*Dn + tid] = acc;
    }
}

// ---------------------------------------------------------------------------
extern "C" void kernel_launch(void* const* d_in, const int* in_sizes, int n_in,
                              void* d_out, int out_size) {
    const int*   user   = (const int*)  d_in[0];
    const int*   item   = (const int*)  d_in[1];
    const int*   query  = (const int*)  d_in[2];
    const float* emb    = (const float*)d_in[3];
    const float* w_self = (const float*)d_in[4];
    const float* b_self = (const float*)d_in[5];
    const float* Wq     = (const float*)d_in[6];
    const float* bq     = (const float*)d_in[7];
    const float* w_red  = (const float*)d_in[8];
    const float* pf     = (const float*)d_in[9];
    float* out = (float*)d_out;

    proj_kernel<<<(VOCAB*32 + 255)/256, 256>>>(emb, w_self, b_self);

    doc_embed_kernel<<<(2*Bx*Rn + Bx)/DPB, 512>>>(user, item, query, emb);

    dim3 g2(NCOL/CT, Bx/BT);   // (64, 8)
    pq_kernel<<<g2, CT>>>(Wq, bq, w_red);

    dim3 g3(Bx, 2);
    attn_kernel<<<g3, Dn>>>(pf, out);
}

// round 17
// speedup vs baseline: 2.1293x; 1.2544x over previous
#include <cuda_runtime.h>
#include <cuda_fp16.h>
#include <math.h>

#define VOCAB 50000
#define Bx 256
#define Rn 20
#define Wn 100
#define Dn 128
#define Hn 64
#define NCOL (Dn*Hn)   // 8192
#define BT 32
#define CT 128
#define DPB 16         // docs per block (one warp each)

// Bit-reinterpret helpers (register moves only).
static __device__ __forceinline__ unsigned h2_to_u32(__half2 h) {
    return *reinterpret_cast<unsigned*>(&h);
}
static __device__ __forceinline__ __half2 u32_to_h2(unsigned u) {
    return *reinterpret_cast<__half2*>(&u);
}

// Scratch (allocation-free rule: __device__ globals)
__device__ float g_user_emb[Bx*Rn*Dn];   // 2.62 MB
__device__ float g_item_emb[Bx*Rn*Dn];   // 2.62 MB
__device__ float g_q_emb[Bx*Dn];         // 128 KB
__device__ float g_V[Bx*Dn];             // 128 KB
__device__ float g_wexp[VOCAB];          // 200 KB: exp(tanh(emb[v].w_self + b))
__device__ uint4 g_emb_h[VOCAB*Dn/8];    // 12.8 MB: fp16 mirror of emb table

// ---------------------------------------------------------------------------
// Kernel 0: per-vocab table pass. One warp per vocab row:
//   wexp[v] = exp(tanh(emb[v].w_self + b_self))  (fp32, exact)
//   g_emb_h[v] = fp16 copy of the row (halves gather L2 traffic).
// ---------------------------------------------------------------------------
__global__ __launch_bounds__(256) void proj_kernel(
        const float* __restrict__ emb,
        const float* __restrict__ w_self,
        const float* __restrict__ b_self) {
    const int gw   = (blockIdx.x*blockDim.x + threadIdx.x) >> 5;
    const int lane = threadIdx.x & 31;
    if (gw >= VOCAB) return;
    const float4 e = *(const float4*)(emb + (size_t)gw*Dn + lane*4);

    // fp16 mirror: 4 floats -> 2x half2 = 8 B per lane (coalesced 256 B/warp).
    uint2 pk;
    pk.x = h2_to_u32(__floats2half2_rn(e.x, e.y));
    pk.y = h2_to_u32(__floats2half2_rn(e.z, e.w));
    ((uint2*)g_emb_h)[(size_t)gw*32 + lane] = pk;

    const float4 w = *(const float4*)(w_self + lane*4);
    float s = e.x*w.x + e.y*w.y + e.z*w.z + e.w*w.w;
    #pragma unroll
    for (int off = 16; off > 0; off >>= 1)
        s += __shfl_xor_sync(0xffffffffu, s, off);
    if (lane == 0) g_wexp[gw] = __expf(tanhf(s + b_self[0]));
}

// ---------------------------------------------------------------------------
// Kernel 1: doc embedding — ONE WARP PER DOC, fp16 gather, zero barriers.
// Pair layout: word 2p in lanes 0-15, word 2p+1 in lanes 16-31; lane l4
// holds dims [l4*8 .. l4*8+7] (8 halves = one uint4 = 16 B). One warp-LDG.128
// covers TWO words (256 B each). fp32 accumulate; softmax normalization
// deferred: out = sum(w_i e_i) / sum(w_i).
// ---------------------------------------------------------------------------
__global__ __launch_bounds__(512, 2) void doc_embed_kernel(
        const int* __restrict__ user,
        const int* __restrict__ item,
        const int* __restrict__ query) {
    __shared__ int2 sp[DPB][Wn];   // (word index, weight bits): 12.8 KB

    const int lane = threadIdx.x & 31;
    const int wid  = threadIdx.x >> 5;               // 0..15
    const int l4   = lane & 15;
    const int hl   = lane >> 4;                      // 0 = word A, 1 = word B
    const int doc  = blockIdx.x * DPB + wid;         // 656*16 = 10496 exact

    const int* words;
    float* outp;
    if (doc < Bx*Rn)        { words = user + doc*Wn;                outp = g_user_emb + doc*Dn; }
    else if (doc < 2*Bx*Rn) { int j = doc - Bx*Rn;   words = item  + j*Wn; outp = g_item_emb + j*Dn; }
    else                    { int j = doc - 2*Bx*Rn; words = query + j*Wn; outp = g_q_emb    + j*Dn; }

    // Stage this doc's indices + weights (per-warp, no block sync).
    for (int k = lane; k < Wn; k += 32) {
        const int w = __ldg(words + k);
        sp[wid][k] = make_int2(w, __float_as_int(__ldg(g_wexp + w)));
    }
    __syncwarp();

    // Main gather: 50 pair-iterations, each one LDG.128 per lane (fp16 row).
    float acc[8] = {0.f,0.f,0.f,0.f,0.f,0.f,0.f,0.f};
    float ssum = 0.f;
    #pragma unroll 10
    for (int p = 0; p < Wn/2; p++) {
        const int2  pr = sp[wid][2*p + hl];      // half-warp uniform LDS
        const float s  = __int_as_float(pr.y);
        const uint4 r  = g_emb_h[(size_t)pr.x*16 + l4];
        const float2 f0 = __half22float2(u32_to_h2(r.x));
        const float2 f1 = __half22float2(u32_to_h2(r.y));
        const float2 f2 = __half22float2(u32_to_h2(r.z));
        const float2 f3 = __half22float2(u32_to_h2(r.w));
        ssum   += s;
        acc[0] += s*f0.x; acc[1] += s*f0.y;
        acc[2] += s*f1.x; acc[3] += s*f1.y;
        acc[4] += s*f2.x; acc[5] += s*f2.y;
        acc[6] += s*f3.x; acc[7] += s*f3.y;
    }

    // Combine word-A/word-B halves (lanes l and l+16 hold the same dims).
    #pragma unroll
    for (int j = 0; j < 8; j++)
        acc[j] += __shfl_xor_sync(0xffffffffu, acc[j], 16);
    ssum += __shfl_xor_sync(0xffffffffu, ssum, 16);

    if (hl == 0) {
        const float inv = 1.f / ssum;
        float4 o0 = make_float4(acc[0]*inv, acc[1]*inv, acc[2]*inv, acc[3]*inv);
        float4 o1 = make_float4(acc[4]*inv, acc[5]*inv, acc[6]*inv, acc[7]*inv);
        *(float4*)(outp + l4*8)     = o0;
        *(float4*)(outp + l4*8 + 4) = o1;
    }
}

// ---------------------------------------------------------------------------
// Kernel 2: fused  V[b,d] = sum_h tanh(q_b . Wq[:, d*64+h] + bq) * w_red[h]
// Batch-tiled GEMM (BT=32 batches reuse each Wq element), col tile CT=128.
// pq (8 MB) is never materialized.
// ---------------------------------------------------------------------------
__global__ void pq_kernel(const float* __restrict__ Wq,
                          const float* __restrict__ bq,
                          const float* __restrict__ w_red) {
    __shared__ __align__(16) float QsT[Dn][BT + 4];   // transposed, padded
    __shared__ float red[BT][CT + 1];

    const int tid  = threadIdx.x;        // 128 threads
    const int col0 = blockIdx.x * CT;
    const int b0   = blockIdx.y * BT;

    #pragma unroll 4
    for (int b = 0; b < BT; b++)
        QsT[tid][b] = g_q_emb[(b0 + b)*Dn + tid];
    __syncthreads();

    float acc[BT];
    #pragma unroll
    for (int b = 0; b < BT; b++) acc[b] = 0.f;

    const int col = col0 + tid;
    const float* wqp = Wq + col;
    #pragma unroll 4
    for (int k = 0; k < Dn; k++) {
        const float wv = wqp[(size_t)k * NCOL];
        const float4* q4 = (const float4*)(&QsT[k][0]);
        #pragma unroll
        for (int i = 0; i < BT/4; i++) {
            float4 q = q4[i];
            acc[4*i+0] += q.x * wv;
            acc[4*i+1] += q.y * wv;
            acc[4*i+2] += q.z * wv;
            acc[4*i+3] += q.w * wv;
        }
    }

    const float bqv = bq[col];
    const float wr  = w_red[col & (Hn-1)];
    #pragma unroll
    for (int b = 0; b < BT; b++)
        red[b][tid] = tanhf(acc[b] + bqv) * wr;
    __syncthreads();

    // Reduce groups of 64 cols: 64 sums, 2 threads each
    const int s    = tid >> 1;      // 0..63
    const int b    = s >> 1;        // 0..31
    const int grp  = s & 1;
    const int part = tid & 1;
    float r = 0.f;
    const int base = grp*64 + part*32;
    #pragma unroll
    for (int j = 0; j < 32; j++) r += red[b][base + j];
    r += __shfl_xor_sync(0xffffffffu, r, 1);
    if (part == 0) {
        const int dd = (col0 >> 6) + grp;
        g_V[(b0 + b)*Dn + dd] = r;
    }
}

// ---------------------------------------------------------------------------
// Kernel 3: review attention — ONE WARP PER (batch, side), zero barriers.
// Score pass: 20 LDG.128 + butterfly dots (all lanes end with every score).
// Softmax + weighted sum entirely in registers; second pass re-reads the
// rows from L1 (guaranteed hits, same SM).
// ---------------------------------------------------------------------------
__global__ __launch_bounds__(64) void attn_kernel(
        const float* __restrict__ pf_ptr,
        float* __restrict__ out) {
    const int lane = threadIdx.x & 31;
    const int gw   = blockIdx.x*2 + (threadIdx.x >> 5);   // 0..511
    const int b    = gw >> 1;
    const int side = gw & 1;

    const float* embp = side ? g_item_emb : g_user_emb;
    const float4 v = *(const float4*)(g_V + b*Dn + lane*4);

    float sc[Rn];
    #pragma unroll
    for (int r = 0; r < Rn; r++) {
        const float4 e = *(const float4*)(embp + (b*Rn + r)*Dn + lane*4);
        float p = e.x*v.x + e.y*v.y + e.z*v.z + e.w*v.w;
        #pragma unroll
        for (int off = 16; off > 0; off >>= 1)
            p += __shfl_xor_sync(0xffffffffu, p, off);
        sc[r] = p;
    }

    float m = sc[0];
    #pragma unroll
    for (int r = 1; r < Rn; r++) m = fmaxf(m, sc[r]);
    float ssum = 0.f;
    #pragma unroll
    for (int r = 0; r < Rn; r++) { sc[r] = __expf(sc[r] - m); ssum += sc[r]; }
    const float inv = 1.f / ssum;

    float4 acc = make_float4(0.f, 0.f, 0.f, 0.f);
    #pragma unroll
    for (int r = 0; r < Rn; r++) {
        const float4 e = *(const float4*)(embp + (b*Rn + r)*Dn + lane*4); // L1 hit
        acc.x += sc[r]*e.x; acc.y += sc[r]*e.y;
        acc.z += sc[r]*e.z; acc.w += sc[r]*e.w;
    }

    if (side == 0) {
        const float pf = pf_ptr[0];
        const float4 q = *(const float4*)(g_q_emb + b*Dn + lane*4);
        float4 o = make_float4(acc.x*inv + pf*q.x, acc.y*inv + pf*q.y,
                               acc.z*inv + pf*q.z, acc.w*inv + pf*q.w);
        *(float4*)(out + b*Dn + lane*4) = o;
    } else {
        float4 o = make_float4(acc.x*inv, acc.y*inv, acc.z*inv, acc.w*inv);
        *(float4*)(out + Bx*Dn + b*Dn + lane*4) = o;
    }
}

// ---------------------------------------------------------------------------
extern "C" void kernel_launch(void* const* d_in, const int* in_sizes, int n_in,
                              void* d_out, int out_size) {
    const int*   user   = (const int*)  d_in[0];
    const int*   item   = (const int*)  d_in[1];
    const int*   query  = (const int*)  d_in[2];
    const float* emb    = (const float*)d_in[3];
    const float* w_self = (const float*)d_in[4];
    const float* b_self = (const float*)d_in[5];
    const float* Wq     = (const float*)d_in[6];
    const float* bq     = (const float*)d_in[7];
    const float* w_red  = (const float*)d_in[8];
    const float* pf     = (const float*)d_in[9];
    float* out = (float*)d_out;

    proj_kernel<<<(VOCAB*32 + 255)/256, 256>>>(emb, w_self, b_self);

    doc_embed_kernel<<<(2*Bx*Rn + Bx)/DPB, 512>>>(user, item, query);

    dim3 g2(NCOL/CT, Bx/BT);   // (64, 8)
    pq_kernel<<<g2, CT>>>(Wq, bq, w_red);

    attn_kernel<<<Bx, 64>>>(pf, out);
}